// round 2
// baseline (speedup 1.0000x reference)
#include <cuda_runtime.h>
#include <math.h>

#define NN 100000
#define NE 1600000

// ---------------- device scratch (no allocations allowed) ----------------
__device__ int   g_is64;
__device__ int   g_src32[NE];
__device__ int   g_dst32[NE];
__device__ int   g_deg_out[NN];
__device__ int   g_deg_in[NN];
__device__ float g_rs_out[NN];
__device__ float g_rs_in[NN];
__device__ float g_h1tmp[(size_t)NN * 128];
__device__ float g_agg1 [(size_t)NN * 128];
__device__ float g_h2tmp[(size_t)NN * 64];
__device__ float g_agg2 [(size_t)NN * 64];
__device__ float g_pre  [(size_t)NN * 128];   // [:,0:64]=a_pre(src part), [:,64:128]=c_pre(dst part)

// ---------------- zero accumulators + degree counters ----------------
__global__ void zero_k() {
    int tid = blockIdx.x * blockDim.x + threadIdx.x;
    int stride = gridDim.x * blockDim.x;
    float4 z = make_float4(0.f, 0.f, 0.f, 0.f);
    float4* a1 = reinterpret_cast<float4*>(g_agg1);
    for (int i = tid; i < NN * 32; i += stride) a1[i] = z;
    float4* a2 = reinterpret_cast<float4*>(g_agg2);
    for (int i = tid; i < NN * 16; i += stride) a2[i] = z;
    for (int i = tid; i < NN; i += stride) { g_deg_out[i] = 0; g_deg_in[i] = 0; }
}

// ---------------- detect index width (int32 vs int64) ----------------
__global__ void detect_k(const void* src) {
    const long long* p = (const long long*)src;
    bool ok = true;
    for (int i = threadIdx.x; i < 256; i += 32) {
        long long v = p[i];
        if (v < 0 || v >= NN) ok = false;
    }
    unsigned m = __ballot_sync(0xffffffffu, ok);
    if (threadIdx.x == 0) g_is64 = (m == 0xffffffffu) ? 1 : 0;
}

// ---------------- normalize indices to int32 + degree histogram ----------------
__global__ void convert_deg_k(const void* srcp, const void* dstp) {
    int e = blockIdx.x * blockDim.x + threadIdx.x;
    if (e >= NE) return;
    int s, d;
    if (g_is64) {
        s = (int)((const long long*)srcp)[e];
        d = (int)((const long long*)dstp)[e];
    } else {
        s = ((const int*)srcp)[e];
        d = ((const int*)dstp)[e];
    }
    g_src32[e] = s;
    g_dst32[e] = d;
    atomicAdd(&g_deg_out[s], 1);
    atomicAdd(&g_deg_in[d], 1);
}

__global__ void rsqrt_k() {
    int n = blockIdx.x * blockDim.x + threadIdx.x;
    if (n >= NN) return;
    g_rs_out[n] = rsqrtf(fmaxf((float)g_deg_out[n], 1.f));
    g_rs_in[n]  = rsqrtf(fmaxf((float)g_deg_in[n],  1.f));
}

// ---------------- generic node GEMM with fused preprocessing ----------------
// PRE: 0 none | 1 A*rs_out | 2 relu(A*rs_in+bias)*rs_out | 3 A*rs_in+bias
// WMAP: 0 W is [K x NOUT] row-major | 1 split map of Wp1[128x64]:
//       Weff[k][j] = j<64 ? Wp1[k][j] : Wp1[64+k][j-64]   (K=64, NOUT=128)
template<int K, int NOUT, int PRE, int WMAP>
__global__ __launch_bounds__(256) void gemm_k(
    const float* __restrict__ A, const float* __restrict__ W,
    const float* __restrict__ bias, float* __restrict__ C)
{
    constexpr int NPT = NOUT / 32;   // cols per thread (4 or 2)
    constexpr int KC  = 32;
    __shared__ float Ws[KC][NOUT];
    __shared__ float Xs[32][KC + 1];
    int tid = threadIdx.x;
    int tx = tid & 31, ty = tid >> 5;
    int nb = blockIdx.x * 32;        // 32 nodes per block (NN % 32 == 0)

    float acc[4][NPT];
#pragma unroll
    for (int r = 0; r < 4; r++)
#pragma unroll
        for (int c = 0; c < NPT; c++) acc[r][c] = 0.f;

    for (int p = 0; p < K / KC; p++) {
        // stage weight chunk
        for (int idx = tid * 4; idx < KC * NOUT; idx += 1024) {
            int kk = idx / NOUT, j = idx % NOUT;
            int k = p * KC + kk;
            float4 w;
            if (WMAP == 0) {
                w = *(const float4*)&W[(size_t)k * NOUT + j];
            } else {
                if (j < 64) w = *(const float4*)&W[k * 64 + j];
                else        w = *(const float4*)&W[(64 + k) * 64 + (j - 64)];
            }
            *(float4*)&Ws[kk][j] = w;
        }
        // stage preprocessed activations
        for (int idx = tid; idx < 32 * KC; idx += 256) {
            int nl = idx >> 5, kk = idx & 31;
            int n = nb + nl;
            int k = p * KC + kk;
            float v = A[(size_t)n * K + k];
            if (PRE == 1)      v *= g_rs_out[n];
            else if (PRE == 2) v = fmaxf(v * g_rs_in[n] + bias[k], 0.f) * g_rs_out[n];
            else if (PRE == 3) v = v * g_rs_in[n] + bias[k];
            Xs[nl][kk] = v;
        }
        __syncthreads();
#pragma unroll
        for (int kk = 0; kk < KC; kk++) {
            float wv[NPT];
            if (NPT == 4) {
                float4 t = *(const float4*)&Ws[kk][tx * 4];
                wv[0] = t.x; wv[1] = t.y; wv[2] = t.z; wv[3] = t.w;
            } else {
                float2 t = *(const float2*)&Ws[kk][tx * 2];
                wv[0] = t.x; wv[1] = t.y;
            }
#pragma unroll
            for (int r = 0; r < 4; r++) {
                float xv = Xs[ty * 4 + r][kk];
#pragma unroll
                for (int c = 0; c < NPT; c++) acc[r][c] = fmaf(xv, wv[c], acc[r][c]);
            }
        }
        __syncthreads();
    }
#pragma unroll
    for (int r = 0; r < 4; r++) {
        int n = nb + ty * 4 + r;
#pragma unroll
        for (int c = 0; c < NPT; c++) C[(size_t)n * NOUT + tx * NPT + c] = acc[r][c];
    }
}

// ---------------- edge scatter: agg[dst] += H[src], vector RED ----------------
template<int DIM>
__global__ __launch_bounds__(256) void scatter_k(const float* __restrict__ H,
                                                 float* __restrict__ AG) {
    constexpr int CH = DIM / 4;
    int tid = blockIdx.x * blockDim.x + threadIdx.x;   // grid sized exactly
    int e = tid / CH, c = tid % CH;
    int s = g_src32[e], d = g_dst32[e];
    float4 v = *(const float4*)&H[(size_t)s * DIM + c * 4];
    float* p = &AG[(size_t)d * DIM + c * 4];
    asm volatile("red.global.add.v4.f32 [%0], {%1,%2,%3,%4};"
                 :: "l"(p), "f"(v.x), "f"(v.y), "f"(v.z), "f"(v.w) : "memory");
}

// ---------------- per-edge MLP: z1 = relu(a[s]+c[d]+bp1); z2; score; sigmoid ----------------
__global__ __launch_bounds__(256) void edge_mlp_k(
    const float* __restrict__ Wp2, const float* __restrict__ bp1,
    const float* __restrict__ bp2, const float* __restrict__ Wp3,
    const float* __restrict__ bp3, float* __restrict__ out)
{
    __shared__ float z1s[64 * 132];   // k-major: z1s[k][edge], stride 132 (pad)
    __shared__ float w2s[64 * 32];
    __shared__ float b1s[64];
    __shared__ float b2s[32];
    __shared__ float w3s[32];
    __shared__ float b3s;
    int tid = threadIdx.x;

    for (int i = tid; i < 64 * 32; i += 256) w2s[i] = Wp2[i];
    if (tid < 64)        b1s[tid]      = bp1[tid];
    else if (tid < 96)   b2s[tid - 64] = bp2[tid - 64];
    else if (tid < 128)  w3s[tid - 96] = Wp3[tid - 96];
    else if (tid == 128) b3s = bp3[0];

    // Phase A: 2 threads per edge build z1 (64 values) into smem (transposed)
    int el = tid >> 1;
    int h  = (tid & 1) * 32;
    int e  = blockIdx.x * 128 + el;   // NE % 128 == 0
    int s = g_src32[e], d = g_dst32[e];
    const float* ps = &g_pre[(size_t)s * 128];
    const float* pd = &g_pre[(size_t)d * 128 + 64];
    __syncthreads();
#pragma unroll
    for (int j4 = 0; j4 < 32; j4 += 4) {
        int j = h + j4;
        float4 a  = *(const float4*)&ps[j];
        float4 b  = *(const float4*)&pd[j];
        float4 bb = *(const float4*)&b1s[j];
        z1s[(j + 0) * 132 + el] = fmaxf(a.x + b.x + bb.x, 0.f);
        z1s[(j + 1) * 132 + el] = fmaxf(a.y + b.y + bb.y, 0.f);
        z1s[(j + 2) * 132 + el] = fmaxf(a.z + b.z + bb.z, 0.f);
        z1s[(j + 3) * 132 + el] = fmaxf(a.w + b.w + bb.w, 0.f);
    }
    __syncthreads();

    // Phase B: Z2 = relu(Z1 @ Wp2 + bp2) as a blocked GEMM; each thread: 4 edges x 4 cols
    int tx = tid & 7;    // col group (4 cols)
    int ey = tid >> 3;   // edge group (4 edges)
    float acc[4][4];
#pragma unroll
    for (int r = 0; r < 4; r++)
#pragma unroll
        for (int c = 0; c < 4; c++) acc[r][c] = 0.f;

#pragma unroll 4
    for (int k = 0; k < 64; k++) {
        float4 w = *(const float4*)&w2s[k * 32 + tx * 4];
        float4 z = *(const float4*)&z1s[k * 132 + ey * 4];
        float zz[4] = { z.x, z.y, z.z, z.w };
        float ww[4] = { w.x, w.y, w.z, w.w };
#pragma unroll
        for (int r = 0; r < 4; r++)
#pragma unroll
            for (int c = 0; c < 4; c++) acc[r][c] = fmaf(zz[r], ww[c], acc[r][c]);
    }

    // Phase C: relu + partial dot with Wp3, reduce across the 8 col-groups
    float4 w3  = *(const float4*)&w3s[tx * 4];
    float4 bb2 = *(const float4*)&b2s[tx * 4];
    float pscore[4];
#pragma unroll
    for (int r = 0; r < 4; r++) {
        float q0 = fmaxf(acc[r][0] + bb2.x, 0.f);
        float q1 = fmaxf(acc[r][1] + bb2.y, 0.f);
        float q2 = fmaxf(acc[r][2] + bb2.z, 0.f);
        float q3 = fmaxf(acc[r][3] + bb2.w, 0.f);
        pscore[r] = q0 * w3.x + q1 * w3.y + q2 * w3.z + q3 * w3.w;
    }
#pragma unroll
    for (int off = 4; off >= 1; off >>= 1)
#pragma unroll
        for (int r = 0; r < 4; r++)
            pscore[r] += __shfl_down_sync(0xffffffffu, pscore[r], off, 8);

    if (tx == 0) {
#pragma unroll
        for (int r = 0; r < 4; r++) {
            float sc = pscore[r] + b3s;
            out[blockIdx.x * 128 + ey * 4 + r] = 1.f / (1.f + expf(-sc));
        }
    }
}

// ---------------- launch ----------------
extern "C" void kernel_launch(void* const* d_in, const int* in_sizes, int n_in,
                              void* d_out, int out_size) {
    const float* x   = (const float*)d_in[0];
    const void*  src = d_in[1];
    const void*  dst = d_in[2];
    const float* W1  = (const float*)d_in[3];
    const float* b1  = (const float*)d_in[4];
    const float* W2  = (const float*)d_in[5];
    const float* b2  = (const float*)d_in[6];
    const float* Wp1 = (const float*)d_in[7];
    const float* bp1 = (const float*)d_in[8];
    const float* Wp2 = (const float*)d_in[9];
    const float* bp2 = (const float*)d_in[10];
    const float* Wp3 = (const float*)d_in[11];
    const float* bp3 = (const float*)d_in[12];
    float* out = (float*)d_out;

    float *h1tmp, *agg1, *h2tmp, *agg2, *pre;
    cudaGetSymbolAddress((void**)&h1tmp, g_h1tmp);
    cudaGetSymbolAddress((void**)&agg1,  g_agg1);
    cudaGetSymbolAddress((void**)&h2tmp, g_h2tmp);
    cudaGetSymbolAddress((void**)&agg2,  g_agg2);
    cudaGetSymbolAddress((void**)&pre,   g_pre);

    zero_k<<<4096, 256>>>();
    detect_k<<<1, 32>>>(src);
    convert_deg_k<<<NE / 256, 256>>>(src, dst);
    rsqrt_k<<<(NN + 255) / 256, 256>>>();

    // layer 1: h1tmp = (x * rs_out) @ W1 ; agg1[dst] += h1tmp[src]
    gemm_k<128, 128, 1, 0><<<NN / 32, 256>>>(x, W1, b1, h1tmp);
    scatter_k<128><<<NE * 32 / 256, 256>>>(h1tmp, agg1);

    // layer 2: h2tmp = (relu(agg1*rs_in + b1) * rs_out) @ W2 ; agg2[dst] += h2tmp[src]
    gemm_k<128, 64, 2, 0><<<NN / 32, 256>>>(agg1, W2, b1, h2tmp);
    scatter_k<64><<<NE * 16 / 256, 256>>>(h2tmp, agg2);

    // predictor precompute: pre = (agg2*rs_in + b2) @ [Wp1_top | Wp1_bot]
    gemm_k<64, 128, 3, 1><<<NN / 32, 256>>>(agg2, Wp1, b2, pre);

    // per-edge MLP + sigmoid
    edge_mlp_k<<<NE / 128, 256>>>(Wp2, bp1, bp2, Wp3, bp3, out);
}

// round 3
// speedup vs baseline: 1.0868x; 1.0868x over previous
#include <cuda_runtime.h>
#include <math.h>

#define NN 100000
#define NE 1600000

// ---------------- device scratch (no allocations allowed) ----------------
__device__ int   g_is64;
__device__ int   g_src32[NE];
__device__ int   g_dst32[NE];
__device__ int   g_deg_out[NN];
__device__ int   g_deg_in[NN];
__device__ float g_rs_out[NN];
__device__ float g_rs_in[NN];
__device__ float g_h1tmp[(size_t)NN * 128];
__device__ float g_agg1 [(size_t)NN * 128];
__device__ float g_h2tmp[(size_t)NN * 64];
__device__ float g_agg2 [(size_t)NN * 64];
__device__ float g_pre  [(size_t)NN * 128];   // [:,0:64]=a_pre(src), [:,64:128]=c_pre(dst)

// ---------------- zero accumulators + degree counters + index-width detect ----------------
__global__ void zero_k(const void* src) {
    int tid = blockIdx.x * blockDim.x + threadIdx.x;
    int stride = gridDim.x * blockDim.x;
    float4 z = make_float4(0.f, 0.f, 0.f, 0.f);
    float4* a1 = reinterpret_cast<float4*>(g_agg1);
    for (int i = tid; i < NN * 32; i += stride) a1[i] = z;
    float4* a2 = reinterpret_cast<float4*>(g_agg2);
    for (int i = tid; i < NN * 16; i += stride) a2[i] = z;
    for (int i = tid; i < NN; i += stride) { g_deg_out[i] = 0; g_deg_in[i] = 0; }
    // index-width detection (first warp of block 0): valid int64 node ids < NN
    if (blockIdx.x == 0 && threadIdx.x < 32) {
        const long long* p = (const long long*)src;
        bool ok = true;
        for (int i = threadIdx.x; i < 256; i += 32) {
            long long v = p[i];
            if (v < 0 || v >= NN) ok = false;
        }
        unsigned m = __ballot_sync(0xffffffffu, ok);
        if (threadIdx.x == 0) g_is64 = (m == 0xffffffffu) ? 1 : 0;
    }
}

// ---------------- normalize indices to int32 + degree histogram ----------------
__global__ void convert_deg_k(const void* srcp, const void* dstp) {
    int e = blockIdx.x * blockDim.x + threadIdx.x;
    if (e >= NE) return;
    int s, d;
    if (g_is64) {
        s = (int)((const long long*)srcp)[e];
        d = (int)((const long long*)dstp)[e];
    } else {
        s = ((const int*)srcp)[e];
        d = ((const int*)dstp)[e];
    }
    g_src32[e] = s;
    g_dst32[e] = d;
    atomicAdd(&g_deg_out[s], 1);
    atomicAdd(&g_deg_in[d], 1);
}

__global__ void rsqrt_k() {
    int n = blockIdx.x * blockDim.x + threadIdx.x;
    if (n >= NN) return;
    g_rs_out[n] = rsqrtf(fmaxf((float)g_deg_out[n], 1.f));
    g_rs_in[n]  = rsqrtf(fmaxf((float)g_deg_in[n],  1.f));
}

// ---------------- node GEMM with fused preprocessing, 1.5 B/FMA blocking ----------------
// PRE: 1 A*rs_out | 2 relu(A*rs_in+bias)*rs_out | 3 A*rs_in+bias
// WMAP: 0 W is [K x NOUT] row-major | 1 split map of Wp1[128x64]:
//       Weff[k][j] = j<64 ? Wp1[k][j] : Wp1[64+k][j-64]   (K=64, NOUT=128)
// Block: 256 threads, NODES rows, TX threads across columns, NPT=NOUT/TX cols/thread,
//        TY=256/TX row-groups, RPT=NODES/TY rows/thread.
template<int K, int NOUT, int NODES, int TX, int PRE, int WMAP>
__global__ __launch_bounds__(256) void gemm_k(
    const float* __restrict__ A, const float* __restrict__ W,
    const float* __restrict__ bias, float* __restrict__ C)
{
    constexpr int NPT = NOUT / TX;
    constexpr int TY  = 256 / TX;
    constexpr int RPT = NODES / TY;
    constexpr int KC  = 32;
    static_assert(NPT == 4 && RPT == 8, "blocking assumption");
    __shared__ float Ws[KC][NOUT];
    __shared__ float Xs[NODES][KC + 1];
    int tid = threadIdx.x;
    int tx = tid % TX, ty = tid / TX;
    int nb = blockIdx.x * NODES;

    float acc[RPT][NPT];
#pragma unroll
    for (int r = 0; r < RPT; r++)
#pragma unroll
        for (int c = 0; c < NPT; c++) acc[r][c] = 0.f;

    for (int p = 0; p < K / KC; p++) {
        // stage weight chunk
        for (int idx = tid * 4; idx < KC * NOUT; idx += 1024) {
            int kk = idx / NOUT, j = idx % NOUT;
            int k = p * KC + kk;
            float4 w;
            if (WMAP == 0) {
                w = *(const float4*)&W[(size_t)k * NOUT + j];
            } else {
                if (j < 64) w = *(const float4*)&W[k * 64 + j];
                else        w = *(const float4*)&W[(64 + k) * 64 + (j - 64)];
            }
            *(float4*)&Ws[kk][j] = w;
        }
        // stage preprocessed activations (coalesced: kk fastest)
        for (int idx = tid; idx < NODES * KC; idx += 256) {
            int nl = idx / KC, kk = idx % KC;
            int n = nb + nl;
            int k = p * KC + kk;
            float v = 0.f;
            if (n < NN) {
                v = A[(size_t)n * K + k];
                if (PRE == 1)      v *= g_rs_out[n];
                else if (PRE == 2) v = fmaxf(v * g_rs_in[n] + bias[k], 0.f) * g_rs_out[n];
                else if (PRE == 3) v = v * g_rs_in[n] + bias[k];
            }
            Xs[nl][kk] = v;
        }
        __syncthreads();
#pragma unroll
        for (int kk = 0; kk < KC; kk++) {
            float4 t = *(const float4*)&Ws[kk][tx * NPT];
            float wv[4] = { t.x, t.y, t.z, t.w };
            float xv[RPT];
#pragma unroll
            for (int r = 0; r < RPT; r++) xv[r] = Xs[ty * RPT + r][kk];
#pragma unroll
            for (int r = 0; r < RPT; r++)
#pragma unroll
                for (int c = 0; c < NPT; c++) acc[r][c] = fmaf(xv[r], wv[c], acc[r][c]);
        }
        __syncthreads();
    }
#pragma unroll
    for (int r = 0; r < RPT; r++) {
        int n = nb + ty * RPT + r;
        if (n < NN) {
            float4 o = make_float4(acc[r][0], acc[r][1], acc[r][2], acc[r][3]);
            *(float4*)&C[(size_t)n * NOUT + tx * NPT] = o;
        }
    }
}

// ---------------- edge scatter: agg[dst] += H[src], vector RED ----------------
template<int DIM>
__global__ __launch_bounds__(256) void scatter_k(const float* __restrict__ H,
                                                 float* __restrict__ AG) {
    constexpr int CH = DIM / 4;
    int tid = blockIdx.x * blockDim.x + threadIdx.x;   // grid sized exactly
    int e = tid / CH, c = tid % CH;
    int s = g_src32[e], d = g_dst32[e];
    float4 v = *(const float4*)&H[(size_t)s * DIM + c * 4];
    float* p = &AG[(size_t)d * DIM + c * 4];
    asm volatile("red.global.add.v4.f32 [%0], {%1,%2,%3,%4};"
                 :: "l"(p), "f"(v.x), "f"(v.y), "f"(v.z), "f"(v.w) : "memory");
}

// ---------------- per-edge MLP: z1 = relu(a[s]+c[d]+bp1); z2; score; sigmoid ----------------
__global__ __launch_bounds__(256) void edge_mlp_k(
    const float* __restrict__ Wp2, const float* __restrict__ bp1,
    const float* __restrict__ bp2, const float* __restrict__ Wp3,
    const float* __restrict__ bp3, float* __restrict__ out)
{
    __shared__ float z1s[64 * 132];   // k-major: z1s[k][edge], stride 132 (pad)
    __shared__ float w2s[64 * 32];
    __shared__ float b1s[64];
    __shared__ float b2s[32];
    __shared__ float w3s[32];
    __shared__ float b3s;
    int tid = threadIdx.x;

    for (int i = tid; i < 64 * 32; i += 256) w2s[i] = Wp2[i];
    if (tid < 64)        b1s[tid]      = bp1[tid];
    else if (tid < 96)   b2s[tid - 64] = bp2[tid - 64];
    else if (tid < 128)  w3s[tid - 96] = Wp3[tid - 96];
    else if (tid == 128) b3s = bp3[0];

    // Phase A: 2 threads per edge build z1 (64 values) into smem (transposed)
    int el = tid >> 1;
    int h  = (tid & 1) * 32;
    int e  = blockIdx.x * 128 + el;   // NE % 128 == 0
    int s = g_src32[e], d = g_dst32[e];
    const float* ps = &g_pre[(size_t)s * 128];
    const float* pd = &g_pre[(size_t)d * 128 + 64];
    __syncthreads();
#pragma unroll
    for (int j4 = 0; j4 < 32; j4 += 4) {
        int j = h + j4;
        float4 a  = *(const float4*)&ps[j];
        float4 b  = *(const float4*)&pd[j];
        float4 bb = *(const float4*)&b1s[j];
        z1s[(j + 0) * 132 + el] = fmaxf(a.x + b.x + bb.x, 0.f);
        z1s[(j + 1) * 132 + el] = fmaxf(a.y + b.y + bb.y, 0.f);
        z1s[(j + 2) * 132 + el] = fmaxf(a.z + b.z + bb.z, 0.f);
        z1s[(j + 3) * 132 + el] = fmaxf(a.w + b.w + bb.w, 0.f);
    }
    __syncthreads();

    // Phase B (128 threads): 8 edges x 4 cols per thread -> 48B smem per 32 FMA
    if (tid < 128) {
        int tx = tid & 7;    // col group (4 cols): 8 groups * 4 = 32 cols
        int ey = tid >> 3;   // edge group (8 edges): 16 groups * 8 = 128 edges
        float acc[8][4];
#pragma unroll
        for (int r = 0; r < 8; r++)
#pragma unroll
            for (int c = 0; c < 4; c++) acc[r][c] = 0.f;

#pragma unroll 4
        for (int k = 0; k < 64; k++) {
            float4 w  = *(const float4*)&w2s[k * 32 + tx * 4];
            float4 z0 = *(const float4*)&z1s[k * 132 + ey * 8];
            float4 z1 = *(const float4*)&z1s[k * 132 + ey * 8 + 4];
            float ww[4] = { w.x, w.y, w.z, w.w };
            float zz[8] = { z0.x, z0.y, z0.z, z0.w, z1.x, z1.y, z1.z, z1.w };
#pragma unroll
            for (int r = 0; r < 8; r++)
#pragma unroll
                for (int c = 0; c < 4; c++) acc[r][c] = fmaf(zz[r], ww[c], acc[r][c]);
        }

        // Phase C: relu + partial dot with Wp3, reduce across the 8 col-groups
        float4 w3  = *(const float4*)&w3s[tx * 4];
        float4 bb2 = *(const float4*)&b2s[tx * 4];
        float pscore[8];
#pragma unroll
        for (int r = 0; r < 8; r++) {
            float q0 = fmaxf(acc[r][0] + bb2.x, 0.f);
            float q1 = fmaxf(acc[r][1] + bb2.y, 0.f);
            float q2 = fmaxf(acc[r][2] + bb2.z, 0.f);
            float q3 = fmaxf(acc[r][3] + bb2.w, 0.f);
            pscore[r] = q0 * w3.x + q1 * w3.y + q2 * w3.z + q3 * w3.w;
        }
#pragma unroll
        for (int off = 4; off >= 1; off >>= 1)
#pragma unroll
            for (int r = 0; r < 8; r++)
                pscore[r] += __shfl_down_sync(0xffffffffu, pscore[r], off, 8);

        if (tx == 0) {
#pragma unroll
            for (int r = 0; r < 8; r++) {
                float sc = pscore[r] + b3s;
                out[blockIdx.x * 128 + ey * 8 + r] = 1.f / (1.f + expf(-sc));
            }
        }
    }
}

// ---------------- launch ----------------
extern "C" void kernel_launch(void* const* d_in, const int* in_sizes, int n_in,
                              void* d_out, int out_size) {
    const float* x   = (const float*)d_in[0];
    const void*  src = d_in[1];
    const void*  dst = d_in[2];
    const float* W1  = (const float*)d_in[3];
    const float* b1  = (const float*)d_in[4];
    const float* W2  = (const float*)d_in[5];
    const float* b2  = (const float*)d_in[6];
    const float* Wp1 = (const float*)d_in[7];
    const float* bp1 = (const float*)d_in[8];
    const float* Wp2 = (const float*)d_in[9];
    const float* bp2 = (const float*)d_in[10];
    const float* Wp3 = (const float*)d_in[11];
    const float* bp3 = (const float*)d_in[12];
    float* out = (float*)d_out;

    float *h1tmp, *agg1, *h2tmp, *agg2, *pre;
    cudaGetSymbolAddress((void**)&h1tmp, g_h1tmp);
    cudaGetSymbolAddress((void**)&agg1,  g_agg1);
    cudaGetSymbolAddress((void**)&h2tmp, g_h2tmp);
    cudaGetSymbolAddress((void**)&agg2,  g_agg2);
    cudaGetSymbolAddress((void**)&pre,   g_pre);

    zero_k<<<4096, 256>>>(src);
    convert_deg_k<<<NE / 256, 256>>>(src, dst);
    rsqrt_k<<<(NN + 255) / 256, 256>>>();

    // layer 1: h1tmp = (x * rs_out) @ W1 ; agg1[dst] += h1tmp[src]
    gemm_k<128, 128, 64, 32, 1, 0><<<(NN + 63) / 64, 256>>>(x, W1, b1, h1tmp);
    scatter_k<128><<<NE * 32 / 256, 256>>>(h1tmp, agg1);

    // layer 2: h2tmp = (relu(agg1*rs_in + b1) * rs_out) @ W2 ; agg2[dst] += h2tmp[src]
    gemm_k<128, 64, 128, 16, 2, 0><<<(NN + 127) / 128, 256>>>(agg1, W2, b1, h2tmp);
    scatter_k<64><<<NE * 16 / 256, 256>>>(h2tmp, agg2);

    // predictor precompute: pre = (agg2*rs_in + b2) @ [Wp1_top | Wp1_bot]
    gemm_k<64, 128, 64, 32, 3, 1><<<(NN + 63) / 64, 256>>>(agg2, Wp1, b2, pre);

    // per-edge MLP + sigmoid
    edge_mlp_k<<<NE / 128, 256>>>(Wp2, bp1, bp2, Wp3, bp3, out);
}

// round 4
// speedup vs baseline: 1.1412x; 1.0500x over previous
#include <cuda_runtime.h>
#include <math.h>

#define NN 100000
#define NE 1600000

// ---------------- device scratch (no allocations allowed) ----------------
__device__ int   g_is64;
__device__ int   g_src32[NE];
__device__ int   g_dst32[NE];
__device__ int   g_deg_out[NN];
__device__ int   g_deg_in[NN];
__device__ float g_rs_out[NN];
__device__ float g_rs_in[NN];
__device__ float g_h1tmp[(size_t)NN * 128];
__device__ float g_agg1 [(size_t)NN * 128];
__device__ float g_h2tmp[(size_t)NN * 64];
__device__ float g_agg2 [(size_t)NN * 64];
__device__ float g_pre  [(size_t)NN * 128];   // [:,0:64]=a_pre(src), [:,64:128]=c_pre(dst)

// ---------------- zero accumulators + degree counters + index-width detect ----------------
__global__ void zero_k(const void* src) {
    int tid = blockIdx.x * blockDim.x + threadIdx.x;
    int stride = gridDim.x * blockDim.x;
    float4 z = make_float4(0.f, 0.f, 0.f, 0.f);
    float4* a1 = reinterpret_cast<float4*>(g_agg1);
    for (int i = tid; i < NN * 32; i += stride) a1[i] = z;
    float4* a2 = reinterpret_cast<float4*>(g_agg2);
    for (int i = tid; i < NN * 16; i += stride) a2[i] = z;
    for (int i = tid; i < NN; i += stride) { g_deg_out[i] = 0; g_deg_in[i] = 0; }
    if (blockIdx.x == 0 && threadIdx.x < 32) {
        const long long* p = (const long long*)src;
        bool ok = true;
        for (int i = threadIdx.x; i < 256; i += 32) {
            long long v = p[i];
            if (v < 0 || v >= NN) ok = false;
        }
        unsigned m = __ballot_sync(0xffffffffu, ok);
        if (threadIdx.x == 0) g_is64 = (m == 0xffffffffu) ? 1 : 0;
    }
}

// ---------------- normalize indices to int32 + degree histogram ----------------
__global__ void convert_deg_k(const void* srcp, const void* dstp) {
    int e = blockIdx.x * blockDim.x + threadIdx.x;
    if (e >= NE) return;
    int s, d;
    if (g_is64) {
        s = (int)((const long long*)srcp)[e];
        d = (int)((const long long*)dstp)[e];
    } else {
        s = ((const int*)srcp)[e];
        d = ((const int*)dstp)[e];
    }
    g_src32[e] = s;
    g_dst32[e] = d;
    atomicAdd(&g_deg_out[s], 1);
    atomicAdd(&g_deg_in[d], 1);
}

__global__ void rsqrt_k() {
    int n = blockIdx.x * blockDim.x + threadIdx.x;
    if (n >= NN) return;
    g_rs_out[n] = rsqrtf(fmaxf((float)g_deg_out[n], 1.f));
    g_rs_in[n]  = rsqrtf(fmaxf((float)g_deg_in[n],  1.f));
}

// ---------------- node GEMM, k-major activation tile (3 LDS / 32 FMA) ----------------
// PRE: 1 A*rs_out | 2 relu(A*rs_in+bias)*rs_out | 3 A*rs_in+bias
// WMAP: 0 W is [K x NOUT] row-major | 1 split map of Wp1[128x64]:
//       Weff[k][j] = j<64 ? Wp1[k][j] : Wp1[64+k][j-64]   (K=64, NOUT=128)
template<int K, int NOUT, int NODES, int TX, int PRE, int WMAP>
__global__ __launch_bounds__(256) void gemm_k(
    const float* __restrict__ A, const float* __restrict__ W,
    const float* __restrict__ bias, float* __restrict__ C)
{
    constexpr int NPT = NOUT / TX;      // 4
    constexpr int TY  = 256 / TX;
    constexpr int RPT = NODES / TY;     // 8
    constexpr int KC  = 32;
    constexpr int KG  = KC / 4;         // 8 float4 groups per node per chunk
    constexpr int XSTR = NODES + 4;     // pad: 4-way conflict on staging stores, 16B-aligned reads
    static_assert(NPT == 4 && RPT == 8, "blocking assumption");
    __shared__ __align__(16) float Ws[KC * NOUT];
    __shared__ __align__(16) float Xs[KC * XSTR];   // k-major: Xs[kk*XSTR + node]
    int tid = threadIdx.x;
    int tx = tid % TX, ty = tid / TX;
    int nb = blockIdx.x * NODES;

    float acc[RPT][NPT];
#pragma unroll
    for (int r = 0; r < RPT; r++)
#pragma unroll
        for (int c = 0; c < NPT; c++) acc[r][c] = 0.f;

    for (int p = 0; p < K / KC; p++) {
        // stage weight chunk (row-major, coalesced)
        for (int idx = tid * 4; idx < KC * NOUT; idx += 1024) {
            int kk = idx / NOUT, j = idx % NOUT;
            int k = p * KC + kk;
            float4 w;
            if (WMAP == 0) {
                w = *(const float4*)&W[(size_t)k * NOUT + j];
            } else {
                if (j < 64) w = *(const float4*)&W[k * 64 + j];
                else        w = *(const float4*)&W[(64 + k) * 64 + (j - 64)];
            }
            *(float4*)&Ws[kk * NOUT + j] = w;
        }
        // stage activations: coalesced float4 gmem read, transposed k-major smem store
        for (int idx = tid; idx < NODES * KG; idx += 256) {
            int nl = idx / KG, kg = idx % KG;
            int n = nb + nl;
            int k = p * KC + kg * 4;
            float v0 = 0.f, v1 = 0.f, v2 = 0.f, v3 = 0.f;
            if (n < NN) {
                float4 t = *(const float4*)&A[(size_t)n * K + k];
                if (PRE == 1) {
                    float ro = g_rs_out[n];
                    v0 = t.x * ro; v1 = t.y * ro; v2 = t.z * ro; v3 = t.w * ro;
                } else if (PRE == 2) {
                    float ri = g_rs_in[n], ro = g_rs_out[n];
                    float4 bb = *(const float4*)&bias[k];
                    v0 = fmaxf(fmaf(t.x, ri, bb.x), 0.f) * ro;
                    v1 = fmaxf(fmaf(t.y, ri, bb.y), 0.f) * ro;
                    v2 = fmaxf(fmaf(t.z, ri, bb.z), 0.f) * ro;
                    v3 = fmaxf(fmaf(t.w, ri, bb.w), 0.f) * ro;
                } else {  // PRE == 3
                    float ri = g_rs_in[n];
                    float4 bb = *(const float4*)&bias[k];
                    v0 = fmaf(t.x, ri, bb.x);
                    v1 = fmaf(t.y, ri, bb.y);
                    v2 = fmaf(t.z, ri, bb.z);
                    v3 = fmaf(t.w, ri, bb.w);
                }
            }
            int kb = kg * 4;
            Xs[(kb + 0) * XSTR + nl] = v0;
            Xs[(kb + 1) * XSTR + nl] = v1;
            Xs[(kb + 2) * XSTR + nl] = v2;
            Xs[(kb + 3) * XSTR + nl] = v3;
        }
        __syncthreads();
#pragma unroll
        for (int kk = 0; kk < KC; kk++) {
            float4 w = *(const float4*)&Ws[kk * NOUT + tx * NPT];
            const float* xp = &Xs[kk * XSTR + ty * RPT];
            float4 x0 = *(const float4*)xp;
            float4 x1 = *(const float4*)(xp + 4);
            float wv[4] = { w.x, w.y, w.z, w.w };
            float xv[8] = { x0.x, x0.y, x0.z, x0.w, x1.x, x1.y, x1.z, x1.w };
#pragma unroll
            for (int r = 0; r < RPT; r++)
#pragma unroll
                for (int c = 0; c < NPT; c++) acc[r][c] = fmaf(xv[r], wv[c], acc[r][c]);
        }
        __syncthreads();
    }
#pragma unroll
    for (int r = 0; r < RPT; r++) {
        int n = nb + ty * RPT + r;
        if (n < NN) {
            float4 o = make_float4(acc[r][0], acc[r][1], acc[r][2], acc[r][3]);
            *(float4*)&C[(size_t)n * NOUT + tx * NPT] = o;
        }
    }
}

// ---------------- edge scatter: agg[dst] += H[src], vector RED ----------------
template<int DIM>
__global__ __launch_bounds__(256) void scatter_k(const float* __restrict__ H,
                                                 float* __restrict__ AG) {
    constexpr int CH = DIM / 4;
    int tid = blockIdx.x * blockDim.x + threadIdx.x;   // grid sized exactly
    int e = tid / CH, c = tid % CH;
    int s = g_src32[e], d = g_dst32[e];
    float4 v = *(const float4*)&H[(size_t)s * DIM + c * 4];
    float* p = &AG[(size_t)d * DIM + c * 4];
    asm volatile("red.global.add.v4.f32 [%0], {%1,%2,%3,%4};"
                 :: "l"(p), "f"(v.x), "f"(v.y), "f"(v.z), "f"(v.w) : "memory");
}

// ---------------- per-edge MLP: z1 = relu(a[s]+c[d]+bp1); z2; score; sigmoid ----------------
__global__ __launch_bounds__(256) void edge_mlp_k(
    const float* __restrict__ Wp2, const float* __restrict__ bp1,
    const float* __restrict__ bp2, const float* __restrict__ Wp3,
    const float* __restrict__ bp3, float* __restrict__ out)
{
    __shared__ float z1s[64 * 132];   // k-major: z1s[k][edge], stride 132 (pad)
    __shared__ float w2s[64 * 32];
    __shared__ float b1s[64];
    __shared__ float b2s[32];
    __shared__ float w3s[32];
    __shared__ float b3s;
    int tid = threadIdx.x;

    for (int i = tid; i < 64 * 32; i += 256) w2s[i] = Wp2[i];
    if (tid < 64)        b1s[tid]      = bp1[tid];
    else if (tid < 96)   b2s[tid - 64] = bp2[tid - 64];
    else if (tid < 128)  w3s[tid - 96] = Wp3[tid - 96];
    else if (tid == 128) b3s = bp3[0];

    // Phase A: 2 threads per edge build z1 (64 values) into smem (transposed)
    int el = tid >> 1;
    int h  = (tid & 1) * 32;
    int e  = blockIdx.x * 128 + el;   // NE % 128 == 0
    int s = g_src32[e], d = g_dst32[e];
    const float* ps = &g_pre[(size_t)s * 128];
    const float* pd = &g_pre[(size_t)d * 128 + 64];
    __syncthreads();
#pragma unroll
    for (int j4 = 0; j4 < 32; j4 += 4) {
        int j = h + j4;
        float4 a  = *(const float4*)&ps[j];
        float4 b  = *(const float4*)&pd[j];
        float4 bb = *(const float4*)&b1s[j];
        z1s[(j + 0) * 132 + el] = fmaxf(a.x + b.x + bb.x, 0.f);
        z1s[(j + 1) * 132 + el] = fmaxf(a.y + b.y + bb.y, 0.f);
        z1s[(j + 2) * 132 + el] = fmaxf(a.z + b.z + bb.z, 0.f);
        z1s[(j + 3) * 132 + el] = fmaxf(a.w + b.w + bb.w, 0.f);
    }
    __syncthreads();

    // Phase B (128 threads): 8 edges x 4 cols per thread
    if (tid < 128) {
        int tx = tid & 7;    // col group (4 cols): 8 groups * 4 = 32 cols
        int ey = tid >> 3;   // edge group (8 edges): 16 groups * 8 = 128 edges
        float acc[8][4];
#pragma unroll
        for (int r = 0; r < 8; r++)
#pragma unroll
            for (int c = 0; c < 4; c++) acc[r][c] = 0.f;

#pragma unroll 4
        for (int k = 0; k < 64; k++) {
            float4 w  = *(const float4*)&w2s[k * 32 + tx * 4];
            float4 z0 = *(const float4*)&z1s[k * 132 + ey * 8];
            float4 z1 = *(const float4*)&z1s[k * 132 + ey * 8 + 4];
            float ww[4] = { w.x, w.y, w.z, w.w };
            float zz[8] = { z0.x, z0.y, z0.z, z0.w, z1.x, z1.y, z1.z, z1.w };
#pragma unroll
            for (int r = 0; r < 8; r++)
#pragma unroll
                for (int c = 0; c < 4; c++) acc[r][c] = fmaf(zz[r], ww[c], acc[r][c]);
        }

        // Phase C: relu + partial dot with Wp3, reduce across the 8 col-groups
        float4 w3  = *(const float4*)&w3s[tx * 4];
        float4 bb2 = *(const float4*)&b2s[tx * 4];
        float pscore[8];
#pragma unroll
        for (int r = 0; r < 8; r++) {
            float q0 = fmaxf(acc[r][0] + bb2.x, 0.f);
            float q1 = fmaxf(acc[r][1] + bb2.y, 0.f);
            float q2 = fmaxf(acc[r][2] + bb2.z, 0.f);
            float q3 = fmaxf(acc[r][3] + bb2.w, 0.f);
            pscore[r] = q0 * w3.x + q1 * w3.y + q2 * w3.z + q3 * w3.w;
        }
#pragma unroll
        for (int off = 4; off >= 1; off >>= 1)
#pragma unroll
            for (int r = 0; r < 8; r++)
                pscore[r] += __shfl_down_sync(0xffffffffu, pscore[r], off, 8);

        if (tx == 0) {
#pragma unroll
            for (int r = 0; r < 8; r++) {
                float sc = pscore[r] + b3s;
                out[blockIdx.x * 128 + ey * 8 + r] = 1.f / (1.f + expf(-sc));
            }
        }
    }
}

// ---------------- launch ----------------
extern "C" void kernel_launch(void* const* d_in, const int* in_sizes, int n_in,
                              void* d_out, int out_size) {
    const float* x   = (const float*)d_in[0];
    const void*  src = d_in[1];
    const void*  dst = d_in[2];
    const float* W1  = (const float*)d_in[3];
    const float* b1  = (const float*)d_in[4];
    const float* W2  = (const float*)d_in[5];
    const float* b2  = (const float*)d_in[6];
    const float* Wp1 = (const float*)d_in[7];
    const float* bp1 = (const float*)d_in[8];
    const float* Wp2 = (const float*)d_in[9];
    const float* bp2 = (const float*)d_in[10];
    const float* Wp3 = (const float*)d_in[11];
    const float* bp3 = (const float*)d_in[12];
    float* out = (float*)d_out;

    float *h1tmp, *agg1, *h2tmp, *agg2, *pre;
    cudaGetSymbolAddress((void**)&h1tmp, g_h1tmp);
    cudaGetSymbolAddress((void**)&agg1,  g_agg1);
    cudaGetSymbolAddress((void**)&h2tmp, g_h2tmp);
    cudaGetSymbolAddress((void**)&agg2,  g_agg2);
    cudaGetSymbolAddress((void**)&pre,   g_pre);

    zero_k<<<4096, 256>>>(src);
    convert_deg_k<<<NE / 256, 256>>>(src, dst);
    rsqrt_k<<<(NN + 255) / 256, 256>>>();

    // layer 1: h1tmp = (x * rs_out) @ W1 ; agg1[dst] += h1tmp[src]
    gemm_k<128, 128, 64, 32, 1, 0><<<(NN + 63) / 64, 256>>>(x, W1, b1, h1tmp);
    scatter_k<128><<<NE * 32 / 256, 256>>>(h1tmp, agg1);

    // layer 2: h2tmp = (relu(agg1*rs_in + b1) * rs_out) @ W2 ; agg2[dst] += h2tmp[src]
    gemm_k<128, 64, 128, 16, 2, 0><<<(NN + 127) / 128, 256>>>(agg1, W2, b1, h2tmp);
    scatter_k<64><<<NE * 16 / 256, 256>>>(h2tmp, agg2);

    // predictor precompute: pre = (agg2*rs_in + b2) @ [Wp1_top | Wp1_bot]
    gemm_k<64, 128, 64, 32, 3, 1><<<(NN + 63) / 64, 256>>>(agg2, Wp1, b2, pre);

    // per-edge MLP + sigmoid
    edge_mlp_k<<<NE / 128, 256>>>(Wp2, bp1, bp2, Wp3, bp3, out);
}

// round 5
// speedup vs baseline: 1.3856x; 1.2141x over previous
#include <cuda_runtime.h>
#include <math.h>

#define NN 100000
#define NE 1600000
#define NBLK_SCAN 98   // ceil(NN/1024)

// ---------------- device scratch (no allocations allowed) ----------------
__device__ int   g_is64;
__device__ int   g_src32[NE];
__device__ int   g_dst32[NE];
__device__ int   g_deg_out[NN];
__device__ int   g_deg_in[NN];
__device__ float g_rs_out[NN];
__device__ float g_rs_in[NN];
__device__ int   g_ptr[NN];        // CSR row offsets (by dst)
__device__ int   g_fill[NN];       // binning cursors
__device__ int   g_bsum[128];      // scan block sums
__device__ int   g_csr_src[NE];    // src node per CSR slot
__device__ float g_h1tmp[(size_t)NN * 128];
__device__ float g_agg1 [(size_t)NN * 128];
__device__ float g_h2tmp[(size_t)NN * 64];
__device__ float g_agg2 [(size_t)NN * 64];
__device__ float g_pre  [(size_t)NN * 128];   // [:,0:64]=a_pre(src), [:,64:128]=c_pre(dst)

// ---------------- zero degree counters + index-width detect ----------------
__global__ void zero_k(const void* src) {
    int tid = blockIdx.x * blockDim.x + threadIdx.x;
    int stride = gridDim.x * blockDim.x;
    for (int i = tid; i < NN; i += stride) { g_deg_out[i] = 0; g_deg_in[i] = 0; }
    if (blockIdx.x == 0 && threadIdx.x < 32) {
        const long long* p = (const long long*)src;
        bool ok = true;
        for (int i = threadIdx.x; i < 256; i += 32) {
            long long v = p[i];
            if (v < 0 || v >= NN) ok = false;
        }
        unsigned m = __ballot_sync(0xffffffffu, ok);
        if (threadIdx.x == 0) g_is64 = (m == 0xffffffffu) ? 1 : 0;
    }
}

// ---------------- normalize indices to int32 + degree histogram ----------------
__global__ void convert_deg_k(const void* srcp, const void* dstp) {
    int e = blockIdx.x * blockDim.x + threadIdx.x;
    if (e >= NE) return;
    int s, d;
    if (g_is64) {
        s = (int)((const long long*)srcp)[e];
        d = (int)((const long long*)dstp)[e];
    } else {
        s = ((const int*)srcp)[e];
        d = ((const int*)dstp)[e];
    }
    g_src32[e] = s;
    g_dst32[e] = d;
    atomicAdd(&g_deg_out[s], 1);
    atomicAdd(&g_deg_in[d], 1);
}

// ---------------- exclusive scan of deg_in (3 kernels) ----------------
__global__ __launch_bounds__(1024) void scanA_k() {
    int n = blockIdx.x * 1024 + threadIdx.x;
    int v = (n < NN) ? g_deg_in[n] : 0;
    int lane = threadIdx.x & 31, wid = threadIdx.x >> 5;
    int x = v;
#pragma unroll
    for (int o = 1; o < 32; o <<= 1) {
        int y = __shfl_up_sync(0xffffffffu, x, o);
        if (lane >= o) x += y;
    }
    __shared__ int wsum[32];
    if (lane == 31) wsum[wid] = x;
    __syncthreads();
    if (wid == 0) {
        int t = wsum[lane];
#pragma unroll
        for (int o = 1; o < 32; o <<= 1) {
            int y = __shfl_up_sync(0xffffffffu, t, o);
            if (lane >= o) t += y;
        }
        wsum[lane] = t;
    }
    __syncthreads();
    int base = (wid > 0) ? wsum[wid - 1] : 0;
    int excl = base + x - v;
    if (n < NN) g_ptr[n] = excl;
    if (threadIdx.x == 1023) g_bsum[blockIdx.x] = excl + v;
}

__global__ void scanB_k() {
    int i = threadIdx.x, lane = i & 31, w = i >> 5;
    int v = (i < NBLK_SCAN) ? g_bsum[i] : 0;
    int x = v;
#pragma unroll
    for (int o = 1; o < 32; o <<= 1) {
        int y = __shfl_up_sync(0xffffffffu, x, o);
        if (lane >= o) x += y;
    }
    __shared__ int ws[4];
    if (lane == 31) ws[w] = x;
    __syncthreads();
    int off = 0;
    for (int k = 0; k < w; k++) off += ws[k];
    if (i < NBLK_SCAN) g_bsum[i] = off + x - v;
}

// fixup + rsqrt + init fill cursors
__global__ void scanC_k() {
    int n = blockIdx.x * 256 + threadIdx.x;
    if (n >= NN) return;
    int p = g_ptr[n] + g_bsum[n >> 10];
    g_ptr[n] = p;
    g_fill[n] = p;
    g_rs_out[n] = rsqrtf(fmaxf((float)g_deg_out[n], 1.f));
    g_rs_in[n]  = rsqrtf(fmaxf((float)g_deg_in[n],  1.f));
}

// ---------------- bin edges by dst ----------------
__global__ void bin_k() {
    int e = blockIdx.x * 256 + threadIdx.x;
    if (e >= NE) return;
    int d = g_dst32[e];
    int slot = atomicAdd(&g_fill[d], 1);
    g_csr_src[slot] = g_src32[e];
}

// ---------------- CSR aggregation: one warp per dst node, no atomics ----------------
template<int DIM>
__global__ __launch_bounds__(256) void agg_k(const float* __restrict__ H,
                                             float* __restrict__ AG) {
    int warp = (blockIdx.x * 256 + threadIdx.x) >> 5;
    if (warp >= NN) return;
    int lane = threadIdx.x & 31;
    int ptr = g_ptr[warp];
    int deg = g_deg_in[warp];
    if (DIM == 128) {
        float4 acc = make_float4(0.f, 0.f, 0.f, 0.f);
        for (int base = 0; base < deg; base += 32) {
            int cnt = min(32, deg - base);
            int idx = (base + lane < deg) ? g_csr_src[ptr + base + lane] : 0;
            for (int j = 0; j < cnt; j++) {
                int s = __shfl_sync(0xffffffffu, idx, j);
                float4 v = *(const float4*)&H[(size_t)s * 128 + lane * 4];
                acc.x += v.x; acc.y += v.y; acc.z += v.z; acc.w += v.w;
            }
        }
        *(float4*)&AG[(size_t)warp * 128 + lane * 4] = acc;
    } else {
        float2 acc = make_float2(0.f, 0.f);
        for (int base = 0; base < deg; base += 32) {
            int cnt = min(32, deg - base);
            int idx = (base + lane < deg) ? g_csr_src[ptr + base + lane] : 0;
            for (int j = 0; j < cnt; j++) {
                int s = __shfl_sync(0xffffffffu, idx, j);
                float2 v = *(const float2*)&H[(size_t)s * 64 + lane * 2];
                acc.x += v.x; acc.y += v.y;
            }
        }
        *(float2*)&AG[(size_t)warp * 64 + lane * 2] = acc;
    }
}

// ---------------- node GEMM, k-major activation tile (3 LDS / 32 FMA) ----------------
// PRE: 1 A*rs_out | 2 relu(A*rs_in+bias)*rs_out | 3 A*rs_in+bias
// WMAP: 0 W is [K x NOUT] row-major | 1 split map of Wp1[128x64]
template<int K, int NOUT, int NODES, int TX, int PRE, int WMAP>
__global__ __launch_bounds__(256) void gemm_k(
    const float* __restrict__ A, const float* __restrict__ W,
    const float* __restrict__ bias, float* __restrict__ C)
{
    constexpr int NPT = NOUT / TX;      // 4
    constexpr int TY  = 256 / TX;
    constexpr int RPT = NODES / TY;     // 8
    constexpr int KC  = 32;
    constexpr int KG  = KC / 4;
    constexpr int XSTR = NODES + 4;
    static_assert(NPT == 4 && RPT == 8, "blocking assumption");
    __shared__ __align__(16) float Ws[KC * NOUT];
    __shared__ __align__(16) float Xs[KC * XSTR];
    int tid = threadIdx.x;
    int tx = tid % TX, ty = tid / TX;
    int nb = blockIdx.x * NODES;

    float acc[RPT][NPT];
#pragma unroll
    for (int r = 0; r < RPT; r++)
#pragma unroll
        for (int c = 0; c < NPT; c++) acc[r][c] = 0.f;

    for (int p = 0; p < K / KC; p++) {
        for (int idx = tid * 4; idx < KC * NOUT; idx += 1024) {
            int kk = idx / NOUT, j = idx % NOUT;
            int k = p * KC + kk;
            float4 w;
            if (WMAP == 0) {
                w = *(const float4*)&W[(size_t)k * NOUT + j];
            } else {
                if (j < 64) w = *(const float4*)&W[k * 64 + j];
                else        w = *(const float4*)&W[(64 + k) * 64 + (j - 64)];
            }
            *(float4*)&Ws[kk * NOUT + j] = w;
        }
        for (int idx = tid; idx < NODES * KG; idx += 256) {
            int nl = idx / KG, kg = idx % KG;
            int n = nb + nl;
            int k = p * KC + kg * 4;
            float v0 = 0.f, v1 = 0.f, v2 = 0.f, v3 = 0.f;
            if (n < NN) {
                float4 t = *(const float4*)&A[(size_t)n * K + k];
                if (PRE == 1) {
                    float ro = g_rs_out[n];
                    v0 = t.x * ro; v1 = t.y * ro; v2 = t.z * ro; v3 = t.w * ro;
                } else if (PRE == 2) {
                    float ri = g_rs_in[n], ro = g_rs_out[n];
                    float4 bb = *(const float4*)&bias[k];
                    v0 = fmaxf(fmaf(t.x, ri, bb.x), 0.f) * ro;
                    v1 = fmaxf(fmaf(t.y, ri, bb.y), 0.f) * ro;
                    v2 = fmaxf(fmaf(t.z, ri, bb.z), 0.f) * ro;
                    v3 = fmaxf(fmaf(t.w, ri, bb.w), 0.f) * ro;
                } else {
                    float ri = g_rs_in[n];
                    float4 bb = *(const float4*)&bias[k];
                    v0 = fmaf(t.x, ri, bb.x);
                    v1 = fmaf(t.y, ri, bb.y);
                    v2 = fmaf(t.z, ri, bb.z);
                    v3 = fmaf(t.w, ri, bb.w);
                }
            }
            int kb = kg * 4;
            Xs[(kb + 0) * XSTR + nl] = v0;
            Xs[(kb + 1) * XSTR + nl] = v1;
            Xs[(kb + 2) * XSTR + nl] = v2;
            Xs[(kb + 3) * XSTR + nl] = v3;
        }
        __syncthreads();
#pragma unroll
        for (int kk = 0; kk < KC; kk++) {
            float4 w = *(const float4*)&Ws[kk * NOUT + tx * NPT];
            const float* xp = &Xs[kk * XSTR + ty * RPT];
            float4 x0 = *(const float4*)xp;
            float4 x1 = *(const float4*)(xp + 4);
            float wv[4] = { w.x, w.y, w.z, w.w };
            float xv[8] = { x0.x, x0.y, x0.z, x0.w, x1.x, x1.y, x1.z, x1.w };
#pragma unroll
            for (int r = 0; r < RPT; r++)
#pragma unroll
                for (int c = 0; c < NPT; c++) acc[r][c] = fmaf(xv[r], wv[c], acc[r][c]);
        }
        __syncthreads();
    }
#pragma unroll
    for (int r = 0; r < RPT; r++) {
        int n = nb + ty * RPT + r;
        if (n < NN) {
            float4 o = make_float4(acc[r][0], acc[r][1], acc[r][2], acc[r][3]);
            *(float4*)&C[(size_t)n * NOUT + tx * NPT] = o;
        }
    }
}

// ---------------- per-edge MLP: z1 = relu(a[s]+c[d]+bp1); z2; score; sigmoid ----------------
__global__ __launch_bounds__(256) void edge_mlp_k(
    const float* __restrict__ Wp2, const float* __restrict__ bp1,
    const float* __restrict__ bp2, const float* __restrict__ Wp3,
    const float* __restrict__ bp3, float* __restrict__ out)
{
    __shared__ float z1s[64 * 132];
    __shared__ float w2s[64 * 32];
    __shared__ float b1s[64];
    __shared__ float b2s[32];
    __shared__ float w3s[32];
    __shared__ float b3s;
    int tid = threadIdx.x;

    for (int i = tid; i < 64 * 32; i += 256) w2s[i] = Wp2[i];
    if (tid < 64)        b1s[tid]      = bp1[tid];
    else if (tid < 96)   b2s[tid - 64] = bp2[tid - 64];
    else if (tid < 128)  w3s[tid - 96] = Wp3[tid - 96];
    else if (tid == 128) b3s = bp3[0];

    int el = tid >> 1;
    int h  = (tid & 1) * 32;
    int e  = blockIdx.x * 128 + el;
    int s = g_src32[e], d = g_dst32[e];
    const float* ps = &g_pre[(size_t)s * 128];
    const float* pd = &g_pre[(size_t)d * 128 + 64];
    __syncthreads();
#pragma unroll
    for (int j4 = 0; j4 < 32; j4 += 4) {
        int j = h + j4;
        float4 a  = *(const float4*)&ps[j];
        float4 b  = *(const float4*)&pd[j];
        float4 bb = *(const float4*)&b1s[j];
        z1s[(j + 0) * 132 + el] = fmaxf(a.x + b.x + bb.x, 0.f);
        z1s[(j + 1) * 132 + el] = fmaxf(a.y + b.y + bb.y, 0.f);
        z1s[(j + 2) * 132 + el] = fmaxf(a.z + b.z + bb.z, 0.f);
        z1s[(j + 3) * 132 + el] = fmaxf(a.w + b.w + bb.w, 0.f);
    }
    __syncthreads();

    if (tid < 128) {
        int tx = tid & 7;
        int ey = tid >> 3;
        float acc[8][4];
#pragma unroll
        for (int r = 0; r < 8; r++)
#pragma unroll
            for (int c = 0; c < 4; c++) acc[r][c] = 0.f;

#pragma unroll 4
        for (int k = 0; k < 64; k++) {
            float4 w  = *(const float4*)&w2s[k * 32 + tx * 4];
            float4 z0 = *(const float4*)&z1s[k * 132 + ey * 8];
            float4 z1 = *(const float4*)&z1s[k * 132 + ey * 8 + 4];
            float ww[4] = { w.x, w.y, w.z, w.w };
            float zz[8] = { z0.x, z0.y, z0.z, z0.w, z1.x, z1.y, z1.z, z1.w };
#pragma unroll
            for (int r = 0; r < 8; r++)
#pragma unroll
                for (int c = 0; c < 4; c++) acc[r][c] = fmaf(zz[r], ww[c], acc[r][c]);
        }

        float4 w3  = *(const float4*)&w3s[tx * 4];
        float4 bb2 = *(const float4*)&b2s[tx * 4];
        float pscore[8];
#pragma unroll
        for (int r = 0; r < 8; r++) {
            float q0 = fmaxf(acc[r][0] + bb2.x, 0.f);
            float q1 = fmaxf(acc[r][1] + bb2.y, 0.f);
            float q2 = fmaxf(acc[r][2] + bb2.z, 0.f);
            float q3 = fmaxf(acc[r][3] + bb2.w, 0.f);
            pscore[r] = q0 * w3.x + q1 * w3.y + q2 * w3.z + q3 * w3.w;
        }
#pragma unroll
        for (int off = 4; off >= 1; off >>= 1)
#pragma unroll
            for (int r = 0; r < 8; r++)
                pscore[r] += __shfl_down_sync(0xffffffffu, pscore[r], off, 8);

        if (tx == 0) {
#pragma unroll
            for (int r = 0; r < 8; r++) {
                float sc = pscore[r] + b3s;
                out[blockIdx.x * 128 + ey * 8 + r] = 1.f / (1.f + expf(-sc));
            }
        }
    }
}

// ---------------- launch ----------------
extern "C" void kernel_launch(void* const* d_in, const int* in_sizes, int n_in,
                              void* d_out, int out_size) {
    const float* x   = (const float*)d_in[0];
    const void*  src = d_in[1];
    const void*  dst = d_in[2];
    const float* W1  = (const float*)d_in[3];
    const float* b1  = (const float*)d_in[4];
    const float* W2  = (const float*)d_in[5];
    const float* b2  = (const float*)d_in[6];
    const float* Wp1 = (const float*)d_in[7];
    const float* bp1 = (const float*)d_in[8];
    const float* Wp2 = (const float*)d_in[9];
    const float* bp2 = (const float*)d_in[10];
    const float* Wp3 = (const float*)d_in[11];
    const float* bp3 = (const float*)d_in[12];
    float* out = (float*)d_out;

    float *h1tmp, *agg1, *h2tmp, *agg2, *pre;
    cudaGetSymbolAddress((void**)&h1tmp, g_h1tmp);
    cudaGetSymbolAddress((void**)&agg1,  g_agg1);
    cudaGetSymbolAddress((void**)&h2tmp, g_h2tmp);
    cudaGetSymbolAddress((void**)&agg2,  g_agg2);
    cudaGetSymbolAddress((void**)&pre,   g_pre);

    zero_k<<<512, 256>>>(src);
    convert_deg_k<<<NE / 256, 256>>>(src, dst);
    // CSR build (by dst) + rsqrt
    scanA_k<<<NBLK_SCAN, 1024>>>();
    scanB_k<<<1, 128>>>();
    scanC_k<<<(NN + 255) / 256, 256>>>();
    bin_k<<<NE / 256, 256>>>();

    // layer 1: h1tmp = (x * rs_out) @ W1 ; agg1 = CSR-sum(h1tmp[src])
    gemm_k<128, 128, 64, 32, 1, 0><<<(NN + 63) / 64, 256>>>(x, W1, b1, h1tmp);
    agg_k<128><<<(NN * 32 + 255) / 256, 256>>>(h1tmp, agg1);

    // layer 2
    gemm_k<128, 64, 128, 16, 2, 0><<<(NN + 127) / 128, 256>>>(agg1, W2, b1, h2tmp);
    agg_k<64><<<(NN * 32 + 255) / 256, 256>>>(h2tmp, agg2);

    // predictor precompute: pre = (agg2*rs_in + b2) @ [Wp1_top | Wp1_bot]
    gemm_k<64, 128, 64, 32, 3, 1><<<(NN + 63) / 64, 256>>>(agg2, Wp1, b2, pre);

    // per-edge MLP + sigmoid
    edge_mlp_k<<<NE / 128, 256>>>(Wp2, bp1, bp2, Wp3, bp3, out);
}